// round 4
// baseline (speedup 1.0000x reference)
#include <cuda_runtime.h>
#include <math.h>

#define NN 50000
#define EE 400000
#define IN_CH 16
#define HID 32
#define KDIM 512          // HID*IN_CH
#define SROW 8192         // KDIM*IN_CH
#define CH 3200           // dst-chunk size
#define NCHUNK 16         // ceil(NN / CH)
#define JSLICE 4
#define JLEN 2048         // SROW / JSLICE

// ---------------- scratch (static device globals; no allocations) ----------------
__device__ float g_S[(size_t)CH * SROW];     // [CH][8192]  ~105 MB
__device__ float g_P[JSLICE * CH * 32];      // split-j partials, 1.6 MB
__device__ float g_Xsum[NN * 16];
__device__ float g_x1[NN * 32];
__device__ float g_xw[NN * 32];
__device__ float g_x2[NN * 32];
__device__ int   g_cnt[NN];
__device__ int   g_offs[NN + 1];
__device__ int   g_cursor[NN];
__device__ int   g_elist[EE];
__device__ int   g_src[EE];
__device__ int   g_dst[EE];
__device__ int   g_is64;

// ---------------- dtype detection: int64 vs int32 edge_index ----------------
__global__ void k_detect(const void* __restrict__ ei) {
    const long long* p = (const long long*)ei;
    int ok = 1;
    #pragma unroll
    for (int i = 0; i < 16; ++i) {
        long long v = p[i];
        if (v < 0 || v >= NN) ok = 0;
    }
    g_is64 = ok;
}

// ---------------- CSR build ----------------
__global__ void k_zero() {
    int i = blockIdx.x * blockDim.x + threadIdx.x;
    if (i < NN) g_cnt[i] = 0;
}

__global__ void k_prep(const void* __restrict__ ei) {
    int e = blockIdx.x * blockDim.x + threadIdx.x;
    if (e >= EE) return;
    int s, d;
    if (g_is64) {
        s = (int)((const long long*)ei)[e];
        d = (int)((const long long*)ei)[EE + e];
    } else {
        s = ((const int*)ei)[e];
        d = ((const int*)ei)[EE + e];
    }
    // defensive clamp (reference guarantees in-range; protects vs crashes)
    s = s < 0 ? 0 : (s >= NN ? NN - 1 : s);
    d = d < 0 ? 0 : (d >= NN ? NN - 1 : d);
    g_src[e] = s;
    g_dst[e] = d;
    atomicAdd(&g_cnt[d], 1);
}

__global__ void k_scan() {
    __shared__ int wsum[32];
    __shared__ int carry;
    int t = threadIdx.x, lane = t & 31, w = t >> 5;
    if (t == 0) carry = 0;
    __syncthreads();
    for (int base = 0; base < NN; base += 1024) {
        int i = base + t;
        int v = (i < NN) ? g_cnt[i] : 0;
        int xv = v;
        #pragma unroll
        for (int off = 1; off < 32; off <<= 1) {
            int y = __shfl_up_sync(0xffffffffu, xv, off);
            if (lane >= off) xv += y;
        }
        if (lane == 31) wsum[w] = xv;
        __syncthreads();
        if (w == 0) {
            int s = wsum[lane];
            #pragma unroll
            for (int off = 1; off < 32; off <<= 1) {
                int y = __shfl_up_sync(0xffffffffu, s, off);
                if (lane >= off) s += y;
            }
            wsum[lane] = s;
        }
        __syncthreads();
        int incl  = xv + (w > 0 ? wsum[w - 1] : 0);
        int total = wsum[31];
        int excl  = incl - v;
        if (i < NN) {
            int o = carry + excl;
            g_offs[i]   = o;
            g_cursor[i] = o;
        }
        __syncthreads();
        if (t == 0) carry += total;
        __syncthreads();
    }
    if (t == 0) g_offs[NN] = carry;
}

__global__ void k_scatter() {
    int e = blockIdx.x * blockDim.x + threadIdx.x;
    if (e >= EE) return;
    int pos = atomicAdd(&g_cursor[g_dst[e]], 1);
    if (pos >= 0 && pos < EE) g_elist[pos] = e;
}

// ---------------- K1: per-dst S row (chunked) ----------------
// S[dl,k,i] = sum_{e:dst=d0+dl} relu(ea@w1+b1)[k] * x[src,i]
// 256 threads; thread t owns k = {2t, 2t+1}; 32 register accumulators.
__global__ __launch_bounds__(256) void k1_build_S(
    const float* __restrict__ x, const float* __restrict__ ea,
    const float* __restrict__ w1, const float* __restrict__ b1,
    int d0, int dn)
{
    int t = threadIdx.x;
    float w1a[16], w1b[16];
    #pragma unroll
    for (int i = 0; i < 16; ++i) {
        w1a[i] = w1[i * KDIM + 2 * t];
        w1b[i] = w1[i * KDIM + 2 * t + 1];
    }
    float b1a = b1[2 * t], b1b = b1[2 * t + 1];

    __shared__ float eas[8][16];
    __shared__ float xss[8][16];

    for (int dl = blockIdx.x; dl < dn; dl += gridDim.x) {
        int d = d0 + dl;
        float Sa[16], Sb[16];
        #pragma unroll
        for (int i = 0; i < 16; ++i) { Sa[i] = 0.f; Sb[i] = 0.f; }
        float xsum = 0.f;

        int beg = g_offs[d], end = g_offs[d + 1];
        for (int base = beg; base < end; base += 8) {
            int nc = end - base; if (nc > 8) nc = 8;
            __syncthreads();
            if (t < 128) {
                int c = t >> 4, i = t & 15;
                if (c < nc) {
                    int e = g_elist[base + c];
                    eas[c][i] = ea[(size_t)e * 16 + i];
                }
            } else {
                int tt = t - 128; int c = tt >> 4, i = tt & 15;
                if (c < nc) {
                    int e = g_elist[base + c];
                    int s = g_src[e];
                    xss[c][i] = x[(size_t)s * 16 + i];
                }
            }
            __syncthreads();
            for (int c = 0; c < nc; ++c) {
                float r0 = b1a, r1 = b1b;
                #pragma unroll
                for (int i = 0; i < 16; ++i) {
                    float ev = eas[c][i];
                    r0 = fmaf(ev, w1a[i], r0);
                    r1 = fmaf(ev, w1b[i], r1);
                }
                r0 = fmaxf(r0, 0.f);
                r1 = fmaxf(r1, 0.f);
                #pragma unroll
                for (int i = 0; i < 16; ++i) {
                    float xv = xss[c][i];
                    Sa[i] = fmaf(r0, xv, Sa[i]);
                    Sb[i] = fmaf(r1, xv, Sb[i]);
                }
                if (t < 16) xsum += xss[c][t];
            }
        }
        float* Sp = g_S + (size_t)dl * SROW + t * 32;
        #pragma unroll
        for (int q = 0; q < 4; ++q)
            ((float4*)Sp)[q] = make_float4(Sa[4*q], Sa[4*q+1], Sa[4*q+2], Sa[4*q+3]);
        #pragma unroll
        for (int q = 0; q < 4; ++q)
            ((float4*)(Sp + 16))[q] = make_float4(Sb[4*q], Sb[4*q+1], Sb[4*q+2], Sb[4*q+3]);
        if (t < 16) g_Xsum[d * 16 + t] = xsum;
    }
}

// ---------------- K2 main: partial GEMM over a j-slice ----------------
// tile = (64 chunk-rows) x (32 o) x (2048 j). 256 threads = 32 o-lanes x 8
// row-groups; thread owns 8 rows x 1 o. Writes g_P[slice][row][o].
__global__ __launch_bounds__(256) void k2_gemm(const float* __restrict__ w2, int dn)
{
    __shared__ float4 As4[64 * 16];    // 64 rows x 64 floats (16 KB)
    __shared__ float  Bs[64 * 32];     // 64 j x 32 o (8 KB)

    int tid = threadIdx.x;
    int o = tid & 31;
    int g = tid >> 5;
    int slice = blockIdx.x & (JSLICE - 1);
    int r0 = (blockIdx.x >> 2) * 64;
    int jbase = slice * JLEN;

    float acc[8];
    #pragma unroll
    for (int r = 0; r < 8; ++r) acc[r] = 0.f;

    for (int chunk = 0; chunk < JLEN / 64; ++chunk) {
        int j0 = jbase + chunk * 64;
        __syncthreads();
        #pragma unroll
        for (int u = 0; u < 4; ++u) {
            int idx = tid + u * 256;
            int row = idx >> 4;
            int q   = idx & 15;
            int rl = r0 + row; if (rl >= dn) rl = dn - 1;
            As4[row * 16 + q] = ((const float4*)(g_S + (size_t)rl * SROW + j0))[q];
        }
        #pragma unroll
        for (int u = 0; u < 8; ++u) {
            int idx = tid + u * 256;
            int jj = idx >> 5;
            int oo = idx & 31;
            int j = j0 + jj;
            Bs[jj * 32 + oo] = w2[(size_t)(j >> 4) * KDIM + (j & 15) * 32 + oo];
        }
        __syncthreads();
        #pragma unroll 4
        for (int q = 0; q < 16; ++q) {
            float bb0 = Bs[(q * 4 + 0) * 32 + o];
            float bb1 = Bs[(q * 4 + 1) * 32 + o];
            float bb2 = Bs[(q * 4 + 2) * 32 + o];
            float bb3 = Bs[(q * 4 + 3) * 32 + o];
            #pragma unroll
            for (int r = 0; r < 8; ++r) {
                float4 a = As4[(g * 8 + r) * 16 + q];
                acc[r] = fmaf(a.x, bb0, fmaf(a.y, bb1, fmaf(a.z, bb2, fmaf(a.w, bb3, acc[r]))));
            }
        }
    }

    #pragma unroll
    for (int r = 0; r < 8; ++r) {
        int rl = r0 + g * 8 + r;
        if (rl < dn)
            g_P[((size_t)slice * CH + rl) * 32 + o] = acc[r];
    }
}

// ---------------- K2 reduce + NNConv epilogue -> x1 ----------------
__global__ void k2_reduce(
    const float* __restrict__ b2, const float* __restrict__ x,
    const float* __restrict__ root, const float* __restrict__ nn_bias,
    int d0, int dn)
{
    int gid = blockIdx.x * blockDim.x + threadIdx.x;
    if (gid >= dn * 32) return;
    int rl = gid >> 5, o = gid & 31;
    int d = d0 + rl;
    float v = nn_bias[o];
    #pragma unroll
    for (int s = 0; s < JSLICE; ++s)
        v += g_P[((size_t)s * CH + rl) * 32 + o];
    #pragma unroll
    for (int i = 0; i < 16; ++i)
        v = fmaf(g_Xsum[d * 16 + i], b2[i * 32 + o], v);
    #pragma unroll
    for (int c = 0; c < 16; ++c)
        v = fmaf(x[(size_t)d * 16 + c], root[c * 32 + o], v);
    g_x1[d * 32 + o] = fmaxf(v, 0.f);
}

// ---------------- K3: xw = x1 @ gcn_w ----------------
__global__ void k3_xw(const float* __restrict__ gcn_w) {
    int gid = blockIdx.x * blockDim.x + threadIdx.x;
    if (gid >= NN * 32) return;
    int d = gid >> 5, o = gid & 31;
    float acc = 0.f;
    #pragma unroll
    for (int c = 0; c < 32; ++c)
        acc = fmaf(g_x1[d * 32 + c], gcn_w[c * 32 + o], acc);
    g_xw[gid] = acc;
}

// ---------------- K4: GCN aggregate via CSR (warp per dst) ----------------
__global__ void k4_gcn(const float* __restrict__ gcn_b) {
    int wid = (blockIdx.x * blockDim.x + threadIdx.x) >> 5;
    int lane = threadIdx.x & 31;
    int nwarps = (gridDim.x * blockDim.x) >> 5;
    for (int d = wid; d < NN; d += nwarps) {
        float dd = rsqrtf((float)(g_cnt[d] + 1));
        float acc = 0.f;
        int beg = g_offs[d], end = g_offs[d + 1];
        for (int j = beg; j < end; ++j) {
            int e = g_elist[j];
            int s = g_src[e];
            float ds = rsqrtf((float)(g_cnt[s] + 1));
            acc = fmaf(ds, g_xw[s * 32 + lane], acc);
        }
        g_x2[d * 32 + lane] = gcn_b[lane] + dd * (dd * g_xw[d * 32 + lane] + acc);
    }
}

// ---------------- K5: edge scorer ----------------
__global__ void k5_score(const float* __restrict__ lin_w, const float* __restrict__ lin_b,
                         float* __restrict__ out) {
    int e = blockIdx.x * blockDim.x + threadIdx.x;
    if (e >= EE) return;
    int s = g_src[e], d = g_dst[e];
    const float4* a = (const float4*)(g_x2 + (size_t)s * 32);
    const float4* b = (const float4*)(g_x2 + (size_t)d * 32);
    const float4* w = (const float4*)lin_w;
    float acc = lin_b[0];
    #pragma unroll
    for (int q = 0; q < 8; ++q) {
        float4 av = a[q], wv = w[q];
        acc += av.x * wv.x + av.y * wv.y + av.z * wv.z + av.w * wv.w;
    }
    #pragma unroll
    for (int q = 0; q < 8; ++q) {
        float4 bv = b[q], wv = w[8 + q];
        acc += bv.x * wv.x + bv.y * wv.y + bv.z * wv.z + bv.w * wv.w;
    }
    out[e] = 1.f / (1.f + expf(-acc));
}

// ---------------- launch ----------------
extern "C" void kernel_launch(void* const* d_in, const int* in_sizes, int n_in,
                              void* d_out, int out_size) {
    const float* x       = (const float*)d_in[0];
    const void*  ei      = d_in[1];
    const float* ea      = (const float*)d_in[2];
    const float* w1      = (const float*)d_in[3];
    const float* b1      = (const float*)d_in[4];
    const float* w2      = (const float*)d_in[5];
    const float* b2      = (const float*)d_in[6];
    const float* root    = (const float*)d_in[7];
    const float* nn_bias = (const float*)d_in[8];
    const float* gcn_w   = (const float*)d_in[9];
    const float* gcn_b   = (const float*)d_in[10];
    const float* lin_w   = (const float*)d_in[11];
    const float* lin_b   = (const float*)d_in[12];
    float*       out     = (float*)d_out;

    k_detect<<<1, 1>>>(ei);
    k_zero<<<(NN + 255) / 256, 256>>>();
    k_prep<<<(EE + 255) / 256, 256>>>(ei);
    k_scan<<<1, 1024>>>();
    k_scatter<<<(EE + 255) / 256, 256>>>();

    for (int c = 0; c < NCHUNK; ++c) {
        int d0 = c * CH;
        int dn = NN - d0; if (dn > CH) dn = CH;
        if (dn <= 0) break;
        int grid1 = dn < 1184 ? dn : 1184;
        k1_build_S<<<grid1, 256>>>(x, ea, w1, b1, d0, dn);
        int rtiles = (dn + 63) / 64;
        k2_gemm<<<rtiles * JSLICE, 256>>>(w2, dn);
        k2_reduce<<<(dn * 32 + 255) / 256, 256>>>(b2, x, root, nn_bias, d0, dn);
    }

    k3_xw<<<(NN * 32 + 255) / 256, 256>>>(gcn_w);
    k4_gcn<<<512, 256>>>(gcn_b);
    k5_score<<<(EE + 255) / 256, 256>>>(lin_w, lin_b, out);
}

// round 6
// speedup vs baseline: 3.0011x; 3.0011x over previous
#include <cuda_runtime.h>
#include <cuda_fp16.h>
#include <math.h>

#define NN 50000
#define EE 400000
#define IN_CH 16
#define HID 32
#define KDIM 512          // HID*IN_CH
#define SROW 8192         // KDIM*IN_CH
#define CH 6400           // dst-chunk size
#define NCHUNK 8
#define JSLICE 8
#define JLEN 1024         // SROW / JSLICE

// ---------------- scratch (static device globals; no allocations) ----------------
__device__ __half g_Sh[(size_t)CH * SROW];    // [CH][8192] fp16  ~105 MB
__device__ __half g_w2t[32 * SROW];           // w2 transposed [o][j'] fp16
__device__ float  g_P[JSLICE * CH * 32];      // split-j partials
__device__ float  g_Xsum[NN * 16];
__device__ float  g_x1[NN * 32];
__device__ float  g_xw[NN * 32];
__device__ float  g_x2[NN * 32];
__device__ float  g_dis[NN];
__device__ int    g_cnt[NN];
__device__ int    g_offs[NN + 1];
__device__ int    g_cursor[NN];
__device__ int    g_elist[EE];
__device__ int    g_src[EE];
__device__ int    g_dst[EE];
__device__ int    g_is64;

// ---------------- dtype detection: int64 vs int32 edge_index ----------------
__global__ void k_detect(const void* __restrict__ ei) {
    const long long* p = (const long long*)ei;
    int ok = 1;
    #pragma unroll
    for (int i = 0; i < 16; ++i) {
        long long v = p[i];
        if (v < 0 || v >= NN) ok = 0;
    }
    g_is64 = ok;
}

// ---------------- CSR build ----------------
__global__ void k_zero() {
    int i = blockIdx.x * blockDim.x + threadIdx.x;
    if (i < NN) g_cnt[i] = 0;
}

__global__ void k_prep(const void* __restrict__ ei) {
    int e = blockIdx.x * blockDim.x + threadIdx.x;
    if (e >= EE) return;
    int s, d;
    if (g_is64) {
        s = (int)((const long long*)ei)[e];
        d = (int)((const long long*)ei)[EE + e];
    } else {
        s = ((const int*)ei)[e];
        d = ((const int*)ei)[EE + e];
    }
    s = s < 0 ? 0 : (s >= NN ? NN - 1 : s);
    d = d < 0 ? 0 : (d >= NN ? NN - 1 : d);
    g_src[e] = s;
    g_dst[e] = d;
    atomicAdd(&g_cnt[d], 1);
}

__global__ void k_scan() {
    __shared__ int wsum[32];
    __shared__ int carry;
    int t = threadIdx.x, lane = t & 31, w = t >> 5;
    if (t == 0) carry = 0;
    __syncthreads();
    for (int base = 0; base < NN; base += 1024) {
        int i = base + t;
        int v = (i < NN) ? g_cnt[i] : 0;
        int xv = v;
        #pragma unroll
        for (int off = 1; off < 32; off <<= 1) {
            int y = __shfl_up_sync(0xffffffffu, xv, off);
            if (lane >= off) xv += y;
        }
        if (lane == 31) wsum[w] = xv;
        __syncthreads();
        if (w == 0) {
            int s = wsum[lane];
            #pragma unroll
            for (int off = 1; off < 32; off <<= 1) {
                int y = __shfl_up_sync(0xffffffffu, s, off);
                if (lane >= off) s += y;
            }
            wsum[lane] = s;
        }
        __syncthreads();
        int incl  = xv + (w > 0 ? wsum[w - 1] : 0);
        int total = wsum[31];
        int excl  = incl - v;
        if (i < NN) {
            int o = carry + excl;
            g_offs[i]   = o;
            g_cursor[i] = o;
        }
        __syncthreads();
        if (t == 0) carry += total;
        __syncthreads();
    }
    if (t == 0) g_offs[NN] = carry;
}

__global__ void k_scatter() {
    int e = blockIdx.x * blockDim.x + threadIdx.x;
    if (e >= EE) return;
    int pos = atomicAdd(&g_cursor[g_dst[e]], 1);
    if (pos >= 0 && pos < EE) g_elist[pos] = e;
}

__global__ void k_dis() {
    int i = blockIdx.x * blockDim.x + threadIdx.x;
    if (i < NN) g_dis[i] = rsqrtf((float)(g_cnt[i] + 1));
}

// ---------------- w2 -> transposed fp16 [o][j'] ----------------
__global__ void k_w2t(const float* __restrict__ w2) {
    int idx = blockIdx.x * blockDim.x + threadIdx.x;
    if (idx >= 32 * SROW) return;
    int o = idx >> 13;          // 0..31
    int j = idx & (SROW - 1);   // 0..8191 ; j = k*16 + i
    g_w2t[idx] = __float2half(w2[(size_t)(j >> 4) * KDIM + (j & 15) * 32 + o]);
}

// ---------------- K1: per-dst S row (chunked), fp16 output ----------------
// S[dl,k,i] = sum_{e:dst=d0+dl} relu(ea@w1+b1)[k] * x[src,i]
// 256 threads; thread t owns k = {2t, 2t+1}.
__global__ __launch_bounds__(256) void k1_build_S(
    const float* __restrict__ x, const float* __restrict__ ea,
    const float* __restrict__ w1, const float* __restrict__ b1,
    int d0, int dn)
{
    int t = threadIdx.x;
    float w1a[16], w1b[16];
    #pragma unroll
    for (int i = 0; i < 16; ++i) {
        w1a[i] = w1[i * KDIM + 2 * t];
        w1b[i] = w1[i * KDIM + 2 * t + 1];
    }
    float b1a = b1[2 * t], b1b = b1[2 * t + 1];

    __shared__ __align__(16) float eas[16][16];
    __shared__ __align__(16) float xss[16][16];

    int lc = t >> 4;   // 0..15 : edge slot this thread loads
    int li = t & 15;   // 0..15 : feature this thread loads

    for (int dl = blockIdx.x; dl < dn; dl += gridDim.x) {
        int d = d0 + dl;
        float Sa[16], Sb[16];
        #pragma unroll
        for (int i = 0; i < 16; ++i) { Sa[i] = 0.f; Sb[i] = 0.f; }
        float xsum = 0.f;

        int beg = g_offs[d], end = g_offs[d + 1];
        for (int base = beg; base < end; base += 16) {
            int nc = end - base; if (nc > 16) nc = 16;
            __syncthreads();
            if (lc < nc) {
                int e = g_elist[base + lc];
                int s = g_src[e];
                eas[lc][li] = ea[(size_t)e * 16 + li];
                xss[lc][li] = x[(size_t)s * 16 + li];
            }
            __syncthreads();
            for (int c = 0; c < nc; ++c) {
                float er[16], xr[16];
                #pragma unroll
                for (int q = 0; q < 4; ++q) {
                    *(float4*)&er[4 * q] = *(const float4*)&eas[c][4 * q];
                    *(float4*)&xr[4 * q] = *(const float4*)&xss[c][4 * q];
                }
                float r0 = b1a, r1 = b1b;
                #pragma unroll
                for (int i = 0; i < 16; ++i) {
                    r0 = fmaf(er[i], w1a[i], r0);
                    r1 = fmaf(er[i], w1b[i], r1);
                }
                r0 = fmaxf(r0, 0.f);
                r1 = fmaxf(r1, 0.f);
                #pragma unroll
                for (int i = 0; i < 16; ++i) {
                    Sa[i] = fmaf(r0, xr[i], Sa[i]);
                    Sb[i] = fmaf(r1, xr[i], Sb[i]);
                }
                if (t < 16) xsum += xss[c][t];
            }
        }
        // pack to fp16 and store 64 bytes (32 halves)
        __align__(16) __half2 hs[16];
        #pragma unroll
        for (int q = 0; q < 8; ++q)
            hs[q] = __float22half2_rn(make_float2(Sa[2 * q], Sa[2 * q + 1]));
        #pragma unroll
        for (int q = 0; q < 8; ++q)
            hs[8 + q] = __float22half2_rn(make_float2(Sb[2 * q], Sb[2 * q + 1]));
        uint4* Sp = (uint4*)(g_Sh + (size_t)dl * SROW + t * 32);
        #pragma unroll
        for (int q = 0; q < 4; ++q) Sp[q] = ((uint4*)hs)[q];
        if (t < 16) g_Xsum[d * 16 + t] = xsum;
    }
}

// ---------------- K2: tensor-core GEMM over a j-slice ----------------
// C[128 rows, 32] += S_h[128, JLEN] @ w2t^T[JLEN, 32] using m16n8k16 HMMA.
// 8 warps, each owns 16 rows. Writes g_P[slice][row][o].
#define AS_STRIDE 72
__global__ __launch_bounds__(256) void k2_mma(int dn)
{
    __shared__ __align__(16) __half As[128 * AS_STRIDE];   // 18432 B
    __shared__ __align__(16) __half Bs[32 * AS_STRIDE];    // 4608 B

    int tid  = threadIdx.x;
    int warp = tid >> 5;
    int lane = tid & 31;
    int g    = lane >> 2;
    int t4   = lane & 3;
    int slice = blockIdx.x & (JSLICE - 1);
    int r0    = (blockIdx.x >> 3) * 128;
    int jbase = slice * JLEN;

    float c0[4], c1[4], c2[4], c3[4];
    #pragma unroll
    for (int nt = 0; nt < 4; ++nt) { c0[nt] = 0.f; c1[nt] = 0.f; c2[nt] = 0.f; c3[nt] = 0.f; }

    for (int it = 0; it < JLEN / 64; ++it) {
        int j0 = jbase + it * 64;
        __syncthreads();
        // stage A: 128 rows x 64 halves (8 uint4/row); 1024 uint4, 4 per thread
        #pragma unroll
        for (int u = 0; u < 4; ++u) {
            int idx = tid + u * 256;
            int row = idx >> 3;
            int q   = idx & 7;
            int rl  = r0 + row; if (rl >= dn) rl = dn - 1;
            *(uint4*)&As[row * AS_STRIDE + q * 8] =
                ((const uint4*)(g_Sh + (size_t)rl * SROW + j0))[q];
        }
        // stage B: 32 rows x 64 halves (8 uint4/row); 256 uint4, 1 per thread
        {
            int row = tid >> 3;
            int q   = tid & 7;
            *(uint4*)&Bs[row * AS_STRIDE + q * 8] =
                ((const uint4*)(g_w2t + (size_t)row * SROW + j0))[q];
        }
        __syncthreads();

        #pragma unroll
        for (int kk = 0; kk < 64; kk += 16) {
            unsigned a0 = *(const unsigned*)&As[(warp * 16 + g    ) * AS_STRIDE + kk     + 2 * t4];
            unsigned a1 = *(const unsigned*)&As[(warp * 16 + g + 8) * AS_STRIDE + kk     + 2 * t4];
            unsigned a2 = *(const unsigned*)&As[(warp * 16 + g    ) * AS_STRIDE + kk + 8 + 2 * t4];
            unsigned a3 = *(const unsigned*)&As[(warp * 16 + g + 8) * AS_STRIDE + kk + 8 + 2 * t4];
            #pragma unroll
            for (int nt = 0; nt < 4; ++nt) {
                unsigned b0 = *(const unsigned*)&Bs[(nt * 8 + g) * AS_STRIDE + kk     + 2 * t4];
                unsigned b1 = *(const unsigned*)&Bs[(nt * 8 + g) * AS_STRIDE + kk + 8 + 2 * t4];
                asm volatile(
                    "mma.sync.aligned.m16n8k16.row.col.f32.f16.f16.f32 "
                    "{%0,%1,%2,%3}, {%4,%5,%6,%7}, {%8,%9}, {%0,%1,%2,%3};"
                    : "+f"(c0[nt]), "+f"(c1[nt]), "+f"(c2[nt]), "+f"(c3[nt])
                    : "r"(a0), "r"(a1), "r"(a2), "r"(a3), "r"(b0), "r"(b1));
            }
        }
    }

    // store: c0,c1 -> row g, cols 2t4,2t4+1 ; c2,c3 -> row g+8
    #pragma unroll
    for (int nt = 0; nt < 4; ++nt) {
        int row = r0 + warp * 16 + g;
        int col = nt * 8 + 2 * t4;
        if (row < dn)
            *(float2*)&g_P[((size_t)slice * CH + row) * 32 + col] = make_float2(c0[nt], c1[nt]);
        if (row + 8 < dn)
            *(float2*)&g_P[((size_t)slice * CH + row + 8) * 32 + col] = make_float2(c2[nt], c3[nt]);
    }
}

// ---------------- K2 reduce + NNConv epilogue -> x1 ----------------
__global__ void k2_reduce(
    const float* __restrict__ b2, const float* __restrict__ x,
    const float* __restrict__ root, const float* __restrict__ nn_bias,
    int d0, int dn)
{
    int gid = blockIdx.x * blockDim.x + threadIdx.x;
    if (gid >= dn * 32) return;
    int rl = gid >> 5, o = gid & 31;
    int d = d0 + rl;
    float v = nn_bias[o];
    #pragma unroll
    for (int s = 0; s < JSLICE; ++s)
        v += g_P[((size_t)s * CH + rl) * 32 + o];
    #pragma unroll
    for (int i = 0; i < 16; ++i)
        v = fmaf(g_Xsum[d * 16 + i], b2[i * 32 + o], v);
    #pragma unroll
    for (int c = 0; c < 16; ++c)
        v = fmaf(x[(size_t)d * 16 + c], root[c * 32 + o], v);
    g_x1[d * 32 + o] = fmaxf(v, 0.f);
}

// ---------------- K3: xw = x1 @ gcn_w ----------------
__global__ void k3_xw(const float* __restrict__ gcn_w) {
    int gid = blockIdx.x * blockDim.x + threadIdx.x;
    if (gid >= NN * 32) return;
    int d = gid >> 5, o = gid & 31;
    float acc = 0.f;
    #pragma unroll
    for (int c = 0; c < 32; ++c)
        acc = fmaf(g_x1[d * 32 + c], gcn_w[c * 32 + o], acc);
    g_xw[gid] = acc;
}

// ---------------- K4: GCN aggregate via CSR (warp per dst) ----------------
__global__ void k4_gcn(const float* __restrict__ gcn_b) {
    int wid = (blockIdx.x * blockDim.x + threadIdx.x) >> 5;
    int lane = threadIdx.x & 31;
    int nwarps = (gridDim.x * blockDim.x) >> 5;
    for (int d = wid; d < NN; d += nwarps) {
        float dd = g_dis[d];
        float acc = 0.f;
        int beg = g_offs[d], end = g_offs[d + 1];
        for (int j = beg; j < end; ++j) {
            int e = g_elist[j];
            int s = g_src[e];
            acc = fmaf(g_dis[s], g_xw[s * 32 + lane], acc);
        }
        g_x2[d * 32 + lane] = gcn_b[lane] + dd * (dd * g_xw[d * 32 + lane] + acc);
    }
}

// ---------------- K5: edge scorer ----------------
__global__ void k5_score(const float* __restrict__ lin_w, const float* __restrict__ lin_b,
                         float* __restrict__ out) {
    int e = blockIdx.x * blockDim.x + threadIdx.x;
    if (e >= EE) return;
    int s = g_src[e], d = g_dst[e];
    const float4* a = (const float4*)(g_x2 + (size_t)s * 32);
    const float4* b = (const float4*)(g_x2 + (size_t)d * 32);
    const float4* w = (const float4*)lin_w;
    float acc = lin_b[0];
    #pragma unroll
    for (int q = 0; q < 8; ++q) {
        float4 av = a[q], wv = w[q];
        acc += av.x * wv.x + av.y * wv.y + av.z * wv.z + av.w * wv.w;
    }
    #pragma unroll
    for (int q = 0; q < 8; ++q) {
        float4 bv = b[q], wv = w[8 + q];
        acc += bv.x * wv.x + bv.y * wv.y + bv.z * wv.z + bv.w * wv.w;
    }
    out[e] = 1.f / (1.f + expf(-acc));
}

// ---------------- launch ----------------
extern "C" void kernel_launch(void* const* d_in, const int* in_sizes, int n_in,
                              void* d_out, int out_size) {
    const float* x       = (const float*)d_in[0];
    const void*  ei      = d_in[1];
    const float* ea      = (const float*)d_in[2];
    const float* w1      = (const float*)d_in[3];
    const float* b1      = (const float*)d_in[4];
    const float* w2      = (const float*)d_in[5];
    const float* b2      = (const float*)d_in[6];
    const float* root    = (const float*)d_in[7];
    const float* nn_bias = (const float*)d_in[8];
    const float* gcn_w   = (const float*)d_in[9];
    const float* gcn_b   = (const float*)d_in[10];
    const float* lin_w   = (const float*)d_in[11];
    const float* lin_b   = (const float*)d_in[12];
    float*       out     = (float*)d_out;

    k_detect<<<1, 1>>>(ei);
    k_zero<<<(NN + 255) / 256, 256>>>();
    k_prep<<<(EE + 255) / 256, 256>>>(ei);
    k_scan<<<1, 1024>>>();
    k_scatter<<<(EE + 255) / 256, 256>>>();   // launch #4; k1 is #5 for ncu

    bool first = true;
    for (int c = 0; c < NCHUNK; ++c) {
        int d0 = c * CH;
        int dn = NN - d0; if (dn > CH) dn = CH;
        if (dn <= 0) break;
        int grid1 = dn < 2048 ? dn : 2048;
        k1_build_S<<<grid1, 256>>>(x, ea, w1, b1, d0, dn);
        if (first) {
            k_w2t<<<(32 * SROW + 255) / 256, 256>>>(w2);
            k_dis<<<(NN + 255) / 256, 256>>>();
            first = false;
        }
        int rtiles = (dn + 127) / 128;
        k2_mma<<<rtiles * JSLICE, 256>>>(dn);
        k2_reduce<<<(dn * 32 + 255) / 256, 256>>>(b2, x, root, nn_bias, d0, dn);
    }

    k3_xw<<<(NN * 32 + 255) / 256, 256>>>(gcn_w);
    k4_gcn<<<512, 256>>>(gcn_b);
    k5_score<<<(EE + 255) / 256, 256>>>(lin_w, lin_b, out);
}

// round 7
// speedup vs baseline: 3.1904x; 1.0631x over previous
#include <cuda_runtime.h>
#include <cuda_fp16.h>
#include <math.h>

#define NN 50000
#define EE 400000
#define IN_CH 16
#define HID 32
#define KDIM 512          // HID*IN_CH
#define SROW 8192         // KDIM*IN_CH
#define CH 3200           // dst-chunk size (S = 52 MB, ~40% of L2)
#define NCHUNK 16
#define JSLICE 8
#define JLEN 1024         // SROW / JSLICE

// ---------------- scratch (static device globals; no allocations) ----------------
__device__ __half g_Sh[(size_t)CH * SROW];    // [CH][8192] fp16  ~52 MB
__device__ __half g_w2t[32 * SROW];           // w2 transposed+permuted [o][j'] fp16
__device__ float  g_P[JSLICE * CH * 32];      // split-j partials
__device__ float  g_Xsum[NN * 16];
__device__ float  g_x1[NN * 32];
__device__ float  g_xw[NN * 32];
__device__ float  g_x2[NN * 32];
__device__ float  g_dis[NN];
__device__ int    g_cnt[NN];
__device__ int    g_offs[NN + 1];
__device__ int    g_cursor[NN];
__device__ int    g_elist[EE];
__device__ int    g_src[EE];
__device__ int    g_dst[EE];
__device__ int    g_is64;

// ---------------- [0] detect dtype + zero counters ----------------
__global__ void k_dz(const void* __restrict__ ei) {
    int i = blockIdx.x * blockDim.x + threadIdx.x;
    if (i < NN) g_cnt[i] = 0;
    if (i == 0) {
        const long long* p = (const long long*)ei;
        int ok = 1;
        #pragma unroll
        for (int q = 0; q < 16; ++q) {
            long long v = p[q];
            if (v < 0 || v >= NN) ok = 0;
        }
        g_is64 = ok;
    }
}

// ---------------- [1] decode edges + histogram ----------------
__global__ void k_prep(const void* __restrict__ ei) {
    int e = blockIdx.x * blockDim.x + threadIdx.x;
    if (e >= EE) return;
    int s, d;
    if (g_is64) {
        s = (int)((const long long*)ei)[e];
        d = (int)((const long long*)ei)[EE + e];
    } else {
        s = ((const int*)ei)[e];
        d = ((const int*)ei)[EE + e];
    }
    s = s < 0 ? 0 : (s >= NN ? NN - 1 : s);
    d = d < 0 ? 0 : (d >= NN ? NN - 1 : d);
    g_src[e] = s;
    g_dst[e] = d;
    atomicAdd(&g_cnt[d], 1);
}

// ---------------- [2] one-pass block scan (1024 thr x 49 elems) ----------------
#define SCAN_PER 49
__global__ void k_scan() {
    __shared__ int wsum[32];
    int t = threadIdx.x, lane = t & 31, w = t >> 5;
    int base = t * SCAN_PER;
    int sum = 0;
    #pragma unroll 7
    for (int i = 0; i < SCAN_PER; ++i) {
        int idx = base + i;
        if (idx < NN) sum += g_cnt[idx];
    }
    int inc = sum;
    #pragma unroll
    for (int off = 1; off < 32; off <<= 1) {
        int y = __shfl_up_sync(0xffffffffu, inc, off);
        if (lane >= off) inc += y;
    }
    if (lane == 31) wsum[w] = inc;
    __syncthreads();
    if (w == 0) {
        int s = wsum[lane];
        #pragma unroll
        for (int off = 1; off < 32; off <<= 1) {
            int y = __shfl_up_sync(0xffffffffu, s, off);
            if (lane >= off) s += y;
        }
        wsum[lane] = s;
    }
    __syncthreads();
    int run = inc - sum + (w > 0 ? wsum[w - 1] : 0);
    #pragma unroll 7
    for (int i = 0; i < SCAN_PER; ++i) {
        int idx = base + i;
        if (idx < NN) {
            int v = g_cnt[idx];
            g_offs[idx]   = run;
            g_cursor[idx] = run;
            run += v;
        }
    }
    if (t == 0) g_offs[NN] = EE;
}

// ---------------- [3] scatter edges into dst-CSR ----------------
__global__ void k_scatter() {
    int e = blockIdx.x * blockDim.x + threadIdx.x;
    if (e >= EE) return;
    int pos = atomicAdd(&g_cursor[g_dst[e]], 1);
    if (pos >= 0 && pos < EE) g_elist[pos] = e;
}

// ---------------- [4] w2 -> transposed/permuted fp16 [o][j'] ----------------
// j' = t*32 + 2*i + c  maps element (k = 2t+c, i);  matches K1's half2 S layout.
__global__ void k_w2t(const float* __restrict__ w2) {
    int idx = blockIdx.x * blockDim.x + threadIdx.x;
    if (idx >= 32 * SROW) return;
    int o  = idx >> 13;           // 0..31
    int jp = idx & (SROW - 1);    // 0..8191
    int tt = jp >> 5;
    int r  = jp & 31;
    int i  = r >> 1;
    int c  = r & 1;
    int k  = 2 * tt + c;
    g_w2t[idx] = __float2half(w2[(size_t)k * KDIM + i * 32 + o]);
}

// ---------------- [5] K1: per-dst S row, half2 datapath ----------------
// Thread t owns k = {2t, 2t+1} packed as half2; S[i] = (S[2t,i], S[2t+1,i]).
__global__ __launch_bounds__(256) void k1_build_S(
    const float* __restrict__ x, const float* __restrict__ ea,
    const float* __restrict__ w1, const float* __restrict__ b1,
    int d0, int dn)
{
    int t = threadIdx.x;
    __half2 w1h[16];
    #pragma unroll
    for (int i = 0; i < 16; ++i)
        w1h[i] = __floats2half2_rn(w1[i * KDIM + 2 * t], w1[i * KDIM + 2 * t + 1]);
    __half2 b1h = __floats2half2_rn(b1[2 * t], b1[2 * t + 1]);
    const __half2 hz = __float2half2_rn(0.f);

    __shared__ __align__(16) __half2 eas[16][16];   // (e,e) duplicated
    __shared__ __align__(16) __half2 xss[16][16];   // (x,x) duplicated

    int lc = t >> 4;   // edge slot this thread loads
    int li = t & 15;   // feature this thread loads

    for (int dl = blockIdx.x; dl < dn; dl += gridDim.x) {
        int d = d0 + dl;
        __half2 S[16];
        #pragma unroll
        for (int i = 0; i < 16; ++i) S[i] = hz;
        float xsum = 0.f;

        int beg = g_offs[d], end = g_offs[d + 1];
        for (int base = beg; base < end; base += 16) {
            int nc = end - base; if (nc > 16) nc = 16;
            __syncthreads();
            if (lc < nc) {
                int e = g_elist[base + lc];
                int s = g_src[e];
                eas[lc][li] = __float2half2_rn(ea[(size_t)e * 16 + li]);
                xss[lc][li] = __float2half2_rn(x[(size_t)s * 16 + li]);
            }
            __syncthreads();
            for (int c = 0; c < nc; ++c) {
                __half2 er[16], xr[16];
                #pragma unroll
                for (int q = 0; q < 4; ++q) {
                    *(uint4*)&er[4 * q] = *(const uint4*)&eas[c][4 * q];
                    *(uint4*)&xr[4 * q] = *(const uint4*)&xss[c][4 * q];
                }
                __half2 rh = b1h;
                #pragma unroll
                for (int i = 0; i < 16; ++i)
                    rh = __hfma2(er[i], w1h[i], rh);
                rh = __hmax2(rh, hz);
                #pragma unroll
                for (int i = 0; i < 16; ++i)
                    S[i] = __hfma2(rh, xr[i], S[i]);
                if (t < 16) xsum += __low2float(xss[c][t]);
            }
        }
        // store 16 half2 = 64 B at row offset t*32 (j' layout matches g_w2t)
        uint4* Sp = (uint4*)(g_Sh + (size_t)dl * SROW + t * 32);
        #pragma unroll
        for (int q = 0; q < 4; ++q) Sp[q] = ((const uint4*)S)[q];
        if (t < 16) g_Xsum[d * 16 + t] = xsum;
    }
}

// ---------------- K2: tensor-core GEMM over a j-slice ----------------
#define AS_STRIDE 72
__global__ __launch_bounds__(256) void k2_mma(int dn)
{
    __shared__ __align__(16) __half As[128 * AS_STRIDE];
    __shared__ __align__(16) __half Bs[32 * AS_STRIDE];

    int tid  = threadIdx.x;
    int warp = tid >> 5;
    int lane = tid & 31;
    int g    = lane >> 2;
    int t4   = lane & 3;
    int slice = blockIdx.x & (JSLICE - 1);
    int r0    = (blockIdx.x >> 3) * 128;
    int jbase = slice * JLEN;

    float c0[4], c1[4], c2[4], c3[4];
    #pragma unroll
    for (int nt = 0; nt < 4; ++nt) { c0[nt] = 0.f; c1[nt] = 0.f; c2[nt] = 0.f; c3[nt] = 0.f; }

    for (int it = 0; it < JLEN / 64; ++it) {
        int j0 = jbase + it * 64;
        __syncthreads();
        #pragma unroll
        for (int u = 0; u < 4; ++u) {
            int idx = tid + u * 256;
            int row = idx >> 3;
            int q   = idx & 7;
            int rl  = r0 + row; if (rl >= dn) rl = dn - 1;
            *(uint4*)&As[row * AS_STRIDE + q * 8] =
                ((const uint4*)(g_Sh + (size_t)rl * SROW + j0))[q];
        }
        {
            int row = tid >> 3;
            int q   = tid & 7;
            *(uint4*)&Bs[row * AS_STRIDE + q * 8] =
                ((const uint4*)(g_w2t + (size_t)row * SROW + j0))[q];
        }
        __syncthreads();

        #pragma unroll
        for (int kk = 0; kk < 64; kk += 16) {
            unsigned a0 = *(const unsigned*)&As[(warp * 16 + g    ) * AS_STRIDE + kk     + 2 * t4];
            unsigned a1 = *(const unsigned*)&As[(warp * 16 + g + 8) * AS_STRIDE + kk     + 2 * t4];
            unsigned a2 = *(const unsigned*)&As[(warp * 16 + g    ) * AS_STRIDE + kk + 8 + 2 * t4];
            unsigned a3 = *(const unsigned*)&As[(warp * 16 + g + 8) * AS_STRIDE + kk + 8 + 2 * t4];
            #pragma unroll
            for (int nt = 0; nt < 4; ++nt) {
                unsigned b0 = *(const unsigned*)&Bs[(nt * 8 + g) * AS_STRIDE + kk     + 2 * t4];
                unsigned b1 = *(const unsigned*)&Bs[(nt * 8 + g) * AS_STRIDE + kk + 8 + 2 * t4];
                asm volatile(
                    "mma.sync.aligned.m16n8k16.row.col.f32.f16.f16.f32 "
                    "{%0,%1,%2,%3}, {%4,%5,%6,%7}, {%8,%9}, {%0,%1,%2,%3};"
                    : "+f"(c0[nt]), "+f"(c1[nt]), "+f"(c2[nt]), "+f"(c3[nt])
                    : "r"(a0), "r"(a1), "r"(a2), "r"(a3), "r"(b0), "r"(b1));
            }
        }
    }

    #pragma unroll
    for (int nt = 0; nt < 4; ++nt) {
        int row = r0 + warp * 16 + g;
        int col = nt * 8 + 2 * t4;
        if (row < dn)
            *(float2*)&g_P[((size_t)slice * CH + row) * 32 + col] = make_float2(c0[nt], c1[nt]);
        if (row + 8 < dn)
            *(float2*)&g_P[((size_t)slice * CH + row + 8) * 32 + col] = make_float2(c2[nt], c3[nt]);
    }
}

// ---------------- K2 reduce + NNConv epilogue -> x1 ----------------
__global__ void k2_reduce(
    const float* __restrict__ b2, const float* __restrict__ x,
    const float* __restrict__ root, const float* __restrict__ nn_bias,
    int d0, int dn)
{
    int gid = blockIdx.x * blockDim.x + threadIdx.x;
    if (gid >= dn * 32) return;
    int rl = gid >> 5, o = gid & 31;
    int d = d0 + rl;
    float v = nn_bias[o];
    #pragma unroll
    for (int s = 0; s < JSLICE; ++s)
        v += g_P[((size_t)s * CH + rl) * 32 + o];
    #pragma unroll
    for (int i = 0; i < 16; ++i)
        v = fmaf(g_Xsum[d * 16 + i], b2[i * 32 + o], v);
    #pragma unroll
    for (int c = 0; c < 16; ++c)
        v = fmaf(x[(size_t)d * 16 + c], root[c * 32 + o], v);
    g_x1[d * 32 + o] = fmaxf(v, 0.f);
}

// ---------------- degree norms ----------------
__global__ void k_dis() {
    int i = blockIdx.x * blockDim.x + threadIdx.x;
    if (i < NN) g_dis[i] = rsqrtf((float)(g_cnt[i] + 1));
}

// ---------------- K3: xw = x1 @ gcn_w ----------------
__global__ void k3_xw(const float* __restrict__ gcn_w) {
    int gid = blockIdx.x * blockDim.x + threadIdx.x;
    if (gid >= NN * 32) return;
    int d = gid >> 5, o = gid & 31;
    float acc = 0.f;
    #pragma unroll
    for (int c = 0; c < 32; ++c)
        acc = fmaf(g_x1[d * 32 + c], gcn_w[c * 32 + o], acc);
    g_xw[gid] = acc;
}

// ---------------- K4: GCN aggregate via CSR (warp per dst) ----------------
__global__ void k4_gcn(const float* __restrict__ gcn_b) {
    int wid = (blockIdx.x * blockDim.x + threadIdx.x) >> 5;
    int lane = threadIdx.x & 31;
    int nwarps = (gridDim.x * blockDim.x) >> 5;
    for (int d = wid; d < NN; d += nwarps) {
        float dd = g_dis[d];
        float acc = 0.f;
        int beg = g_offs[d], end = g_offs[d + 1];
        for (int j = beg; j < end; ++j) {
            int e = g_elist[j];
            int s = g_src[e];
            acc = fmaf(g_dis[s], g_xw[s * 32 + lane], acc);
        }
        g_x2[d * 32 + lane] = gcn_b[lane] + dd * (dd * g_xw[d * 32 + lane] + acc);
    }
}

// ---------------- K5: edge scorer ----------------
__global__ void k5_score(const float* __restrict__ lin_w, const float* __restrict__ lin_b,
                         float* __restrict__ out) {
    int e = blockIdx.x * blockDim.x + threadIdx.x;
    if (e >= EE) return;
    int s = g_src[e], d = g_dst[e];
    const float4* a = (const float4*)(g_x2 + (size_t)s * 32);
    const float4* b = (const float4*)(g_x2 + (size_t)d * 32);
    const float4* w = (const float4*)lin_w;
    float acc = lin_b[0];
    #pragma unroll
    for (int q = 0; q < 8; ++q) {
        float4 av = a[q], wv = w[q];
        acc += av.x * wv.x + av.y * wv.y + av.z * wv.z + av.w * wv.w;
    }
    #pragma unroll
    for (int q = 0; q < 8; ++q) {
        float4 bv = b[q], wv = w[8 + q];
        acc += bv.x * wv.x + bv.y * wv.y + bv.z * wv.z + bv.w * wv.w;
    }
    out[e] = 1.f / (1.f + expf(-acc));
}

// ---------------- launch ----------------
extern "C" void kernel_launch(void* const* d_in, const int* in_sizes, int n_in,
                              void* d_out, int out_size) {
    const float* x       = (const float*)d_in[0];
    const void*  ei      = d_in[1];
    const float* ea      = (const float*)d_in[2];
    const float* w1      = (const float*)d_in[3];
    const float* b1      = (const float*)d_in[4];
    const float* w2      = (const float*)d_in[5];
    const float* b2      = (const float*)d_in[6];
    const float* root    = (const float*)d_in[7];
    const float* nn_bias = (const float*)d_in[8];
    const float* gcn_w   = (const float*)d_in[9];
    const float* gcn_b   = (const float*)d_in[10];
    const float* lin_w   = (const float*)d_in[11];
    const float* lin_b   = (const float*)d_in[12];
    float*       out     = (float*)d_out;

    k_dz<<<(NN + 255) / 256, 256>>>(ei);                      // launch 0
    k_prep<<<(EE + 255) / 256, 256>>>(ei);                    // 1
    k_scan<<<1, 1024>>>();                                    // 2
    k_scatter<<<(EE + 255) / 256, 256>>>();                   // 3
    k_w2t<<<(32 * SROW + 255) / 256, 256>>>(w2);              // 4

    for (int c = 0; c < NCHUNK; ++c) {
        int d0 = c * CH;
        int dn = NN - d0; if (dn > CH) dn = CH;
        if (dn <= 0) break;
        int grid1 = dn < 2048 ? dn : 2048;
        k1_build_S<<<grid1, 256>>>(x, ea, w1, b1, d0, dn);    // chunk0: launch 5 (ncu)
        int rtiles = (dn + 127) / 128;
        k2_mma<<<rtiles * JSLICE, 256>>>(dn);
        k2_reduce<<<(dn * 32 + 255) / 256, 256>>>(b2, x, root, nn_bias, d0, dn);
    }

    k_dis<<<(NN + 255) / 256, 256>>>();
    k3_xw<<<(NN * 32 + 255) / 256, 256>>>(gcn_w);
    k4_gcn<<<512, 256>>>(gcn_b);
    k5_score<<<(EE + 255) / 256, 256>>>(lin_w, lin_b, out);
}